// round 11
// baseline (speedup 1.0000x reference)
#include <cuda_runtime.h>
#include <math.h>
#include <stdint.h>

#define N_NODES 50000
#define E_EDGES 800000
#define TOT_E   (E_EDGES + N_NODES)
#define IN_C    768
#define HID     64
#define OUT_C   8
#define BN_EPS  1e-5f
#define NEG_SLOPE 0.2f
#define FULL    0xffffffffu

// ---------------- scratch (device globals: no allocation allowed) ----------
__device__ float g_h0[N_NODES * HID];   // post proj+bn1+elu (identity 1)
__device__ float g_xw[N_NODES * HID];   // per-conv transformed features
__device__ float g_asrc[N_NODES * 8];
__device__ float g_adst[N_NODES * 8];
__device__ float g_conv[N_NODES * HID]; // conv output (incl. bias)
__device__ float g_h1[N_NODES * HID];
__device__ float g_h2[N_NODES * HID];

__device__ int g_cnt[N_NODES];          // zeroed by scatter for next call
__device__ int g_cur[N_NODES];          // zeroed by count at start of call
__device__ int g_off[N_NODES + 1];
__device__ int g_esrc[TOT_E];

#define SCAN_BLOCKS 49   // ceil(50000/1024)
__device__ int g_blksum[SCAN_BLOCKS];

// ---------------- CSR build ----------------
__global__ void count_kernel(const int* __restrict__ ei) {
    int e = blockIdx.x * blockDim.x + threadIdx.x;
    if (e < N_NODES) g_cur[e] = 0;
    if (e >= TOT_E) return;
    int d = (e < E_EDGES) ? ei[E_EDGES + e] : (e - E_EDGES);
    atomicAdd(&g_cnt[d], 1);
}

__global__ void scanA_kernel() {
    __shared__ int sm[32];
    int tid = threadIdx.x;
    int idx = blockIdx.x * 1024 + tid;
    int v = (idx < N_NODES) ? g_cnt[idx] : 0;
    #pragma unroll
    for (int o = 16; o; o >>= 1) v += __shfl_xor_sync(FULL, v, o);
    if ((tid & 31) == 0) sm[tid >> 5] = v;
    __syncthreads();
    if (tid < 32) {
        int t = sm[tid];
        #pragma unroll
        for (int o = 16; o; o >>= 1) t += __shfl_xor_sync(FULL, t, o);
        if (tid == 0) g_blksum[blockIdx.x] = t;
    }
}

__global__ void scanB_kernel() {
    int run = 0;
    for (int b = 0; b < SCAN_BLOCKS; b++) {
        int t = g_blksum[b];
        g_blksum[b] = run;
        run += t;
    }
    g_off[N_NODES] = TOT_E;
}

__global__ void scanC_kernel() {
    __shared__ int warpsum[32];
    int tid = threadIdx.x;
    int idx = blockIdx.x * 1024 + tid;
    int v = (idx < N_NODES) ? g_cnt[idx] : 0;
    int x = v;
    #pragma unroll
    for (int o = 1; o < 32; o <<= 1) {
        int t = __shfl_up_sync(FULL, x, o);
        if ((tid & 31) >= o) x += t;
    }
    if ((tid & 31) == 31) warpsum[tid >> 5] = x;
    __syncthreads();
    if (tid < 32) {
        int w = warpsum[tid];
        int s = w;
        #pragma unroll
        for (int o = 1; o < 32; o <<= 1) {
            int t = __shfl_up_sync(FULL, s, o);
            if (tid >= o) s += t;
        }
        warpsum[tid] = s - w;   // exclusive warp base
    }
    __syncthreads();
    int excl = (x - v) + warpsum[tid >> 5] + g_blksum[blockIdx.x];
    if (idx < N_NODES) g_off[idx] = excl;
}

__global__ void scatter_kernel(const int* __restrict__ ei) {
    int e = blockIdx.x * blockDim.x + threadIdx.x;
    if (e < N_NODES) g_cnt[e] = 0;   // reset for next call
    if (e >= TOT_E) return;
    int s, d;
    if (e < E_EDGES) { s = ei[e]; d = ei[E_EDGES + e]; }
    else { s = e - E_EDGES; d = s; }
    int pos = g_off[d] + atomicAdd(&g_cur[d], 1);
    g_esrc[pos] = s;
}

// ---------------- projection GEMM (x @ proj_W + b) -> BN1 -> ELU ----------
// Double-buffered: one __syncthreads per K-chunk, global loads overlapped
// with the compute of the previous chunk.
__global__ __launch_bounds__(256) void proj_kernel(
    const float* __restrict__ x, const float* __restrict__ W,
    const float* __restrict__ pb,
    const float* __restrict__ bg, const float* __restrict__ bb,
    const float* __restrict__ bm, const float* __restrict__ bv)
{
    __shared__ float As[2][16][132];  // [buf][k][m], padded
    __shared__ float Bs[2][16][64];   // [buf][k][n]
    int tid = threadIdx.x;
    int tx = tid & 15, ty = tid >> 4;
    int row0 = blockIdx.x * 128;

    // load-phase indexing (constant across chunks)
    int lr0 = (tid) >> 2,        lc0 = (tid) & 3;          // A part 0
    int lr1 = (tid + 256) >> 2,  lc1 = (tid + 256) & 3;    // A part 1
    int bk  = tid >> 4,          bc4 = tid & 15;           // B
    int garow0 = row0 + lr0, garow1 = row0 + lr1;
    const float* xr0 = x + (size_t)garow0 * IN_C + lc0 * 4;
    const float* xr1 = x + (size_t)garow1 * IN_C + lc1 * 4;
    const float* wr  = W + (size_t)bk * 64 + bc4 * 4;

    float4 ra0, ra1, rb;
    // prologue: chunk 0 -> buffer 0
    ra0 = (garow0 < N_NODES) ? *(const float4*)(xr0)
                             : make_float4(0.f, 0.f, 0.f, 0.f);
    ra1 = (garow1 < N_NODES) ? *(const float4*)(xr1)
                             : make_float4(0.f, 0.f, 0.f, 0.f);
    rb  = *(const float4*)(wr);
    As[0][lc0 * 4 + 0][lr0] = ra0.x; As[0][lc0 * 4 + 1][lr0] = ra0.y;
    As[0][lc0 * 4 + 2][lr0] = ra0.z; As[0][lc0 * 4 + 3][lr0] = ra0.w;
    As[0][lc1 * 4 + 0][lr1] = ra1.x; As[0][lc1 * 4 + 1][lr1] = ra1.y;
    As[0][lc1 * 4 + 2][lr1] = ra1.z; As[0][lc1 * 4 + 3][lr1] = ra1.w;
    *(float4*)&Bs[0][bk][bc4 * 4] = rb;
    __syncthreads();

    float acc[8][4];
    #pragma unroll
    for (int i = 0; i < 8; i++)
        #pragma unroll
        for (int j = 0; j < 4; j++) acc[i][j] = 0.f;

    #define NCHUNK (IN_C / 16)
    for (int c = 0; c < NCHUNK; c++) {
        int cur = c & 1, nxt = cur ^ 1;
        if (c < NCHUNK - 1) {
            int k0 = (c + 1) * 16;
            ra0 = (garow0 < N_NODES) ? *(const float4*)(xr0 + k0)
                                     : make_float4(0.f, 0.f, 0.f, 0.f);
            ra1 = (garow1 < N_NODES) ? *(const float4*)(xr1 + k0)
                                     : make_float4(0.f, 0.f, 0.f, 0.f);
            rb  = *(const float4*)(wr + (size_t)k0 * 64);
        }
        #pragma unroll
        for (int k = 0; k < 16; k++) {
            float4 a0 = *(float4*)&As[cur][k][ty * 8];
            float4 a1 = *(float4*)&As[cur][k][ty * 8 + 4];
            float4 b  = *(float4*)&Bs[cur][k][tx * 4];
            float ar[8] = {a0.x, a0.y, a0.z, a0.w, a1.x, a1.y, a1.z, a1.w};
            float br[4] = {b.x, b.y, b.z, b.w};
            #pragma unroll
            for (int i = 0; i < 8; i++)
                #pragma unroll
                for (int j = 0; j < 4; j++)
                    acc[i][j] = fmaf(ar[i], br[j], acc[i][j]);
        }
        if (c < NCHUNK - 1) {
            As[nxt][lc0 * 4 + 0][lr0] = ra0.x; As[nxt][lc0 * 4 + 1][lr0] = ra0.y;
            As[nxt][lc0 * 4 + 2][lr0] = ra0.z; As[nxt][lc0 * 4 + 3][lr0] = ra0.w;
            As[nxt][lc1 * 4 + 0][lr1] = ra1.x; As[nxt][lc1 * 4 + 1][lr1] = ra1.y;
            As[nxt][lc1 * 4 + 2][lr1] = ra1.z; As[nxt][lc1 * 4 + 3][lr1] = ra1.w;
            *(float4*)&Bs[nxt][bk][bc4 * 4] = rb;
        }
        __syncthreads();
    }
    #undef NCHUNK

    float sc[4], sh[4], pbv[4];
    #pragma unroll
    for (int j = 0; j < 4; j++) {
        int col = tx * 4 + j;
        float s = bg[col] * rsqrtf(bv[col] + BN_EPS);
        sc[j] = s;
        sh[j] = bb[col] - bm[col] * s;
        pbv[j] = pb[col];
    }
    #pragma unroll
    for (int i = 0; i < 8; i++) {
        int grow = row0 + ty * 8 + i;
        if (grow < N_NODES) {
            float vj[4];
            #pragma unroll
            for (int j = 0; j < 4; j++) {
                float v = (acc[i][j] + pbv[j]) * sc[j] + sh[j];
                vj[j] = v > 0.f ? v : expm1f(v);
            }
            *(float4*)&g_h0[(size_t)grow * 64 + tx * 4] =
                make_float4(vj[0], vj[1], vj[2], vj[3]);
        }
    }
}

// ---------------- 64x64 feature transform: g_xw = hin @ W ----------------
__global__ __launch_bounds__(256) void xw64_kernel(int which_in,
                                                   const float* __restrict__ W)
{
    const float* hin = which_in == 0 ? g_h0 : g_h1;
    __shared__ float Hs[64][65];
    __shared__ float Ws[64][64];
    int tid = threadIdx.x;
    int row0 = blockIdx.x * 64;

    for (int i = tid; i < 64 * 64; i += 256) {
        int r = i >> 6, c = i & 63;
        Ws[r][c] = W[i];
        int node = row0 + r;
        Hs[r][c] = (node < N_NODES) ? hin[(size_t)node * 64 + c] : 0.f;
    }
    __syncthreads();

    int r = tid >> 2, q = tid & 3;
    float acc[16];
    #pragma unroll
    for (int j = 0; j < 16; j++) acc[j] = 0.f;

    #pragma unroll 8
    for (int k = 0; k < 64; k++) {
        float hv = Hs[r][k];
        #pragma unroll
        for (int j = 0; j < 4; j++) {
            float4 w = *(float4*)&Ws[k][q * 16 + j * 4];
            acc[j * 4 + 0] = fmaf(hv, w.x, acc[j * 4 + 0]);
            acc[j * 4 + 1] = fmaf(hv, w.y, acc[j * 4 + 1]);
            acc[j * 4 + 2] = fmaf(hv, w.z, acc[j * 4 + 2]);
            acc[j * 4 + 3] = fmaf(hv, w.w, acc[j * 4 + 3]);
        }
    }
    int node = row0 + r;
    if (node < N_NODES) {
        #pragma unroll
        for (int j = 0; j < 4; j++)
            *(float4*)&g_xw[(size_t)node * 64 + q * 16 + j * 4] =
                make_float4(acc[j * 4], acc[j * 4 + 1], acc[j * 4 + 2], acc[j * 4 + 3]);
    }
}

// ---------------- attention coefficients ----------------
template <int H>
__global__ void att_kernel(const float* __restrict__ att_s,
                           const float* __restrict__ att_d)
{
    const int C = 64 / H;
    int t = blockIdx.x * blockDim.x + threadIdx.x;
    if (t >= N_NODES * H) return;
    int n = t / H, h = t % H;
    const float* row = &g_xw[(size_t)n * 64 + h * C];
    float ss = 0.f, sd = 0.f;
    #pragma unroll
    for (int c = 0; c < C; c++) {
        float v = row[c];
        ss = fmaf(v, __ldg(&att_s[h * C + c]), ss);
        sd = fmaf(v, __ldg(&att_d[h * C + c]), sd);
    }
    g_asrc[t] = ss;
    g_adst[t] = sd;
}

// ---- GAT gather: one warp per destination node (single pass, no-max softmax) ----
template <int H>
__global__ void gather_kernel(const float* __restrict__ bias)
{
    int wid = (blockIdx.x * blockDim.x + threadIdx.x) >> 5;
    if (wid >= N_NODES) return;
    int lane = threadIdx.x & 31;
    int beg = g_off[wid], end = g_off[wid + 1];

    float acc0 = 0.f, acc1 = 0.f;

    if (H == 8) {
        int sub = lane >> 3, h = lane & 7;
        float ad = (lane < 8) ? g_adst[(size_t)wid * 8 + lane] : 0.f;
        float adv = __shfl_sync(FULL, ad, h);

        float den = 0.f;
        for (int base = beg; base < end; base += 4) {
            int e = base + sub;
            bool v = e < end;
            int s = v ? g_esrc[e] : 0;
            float al = g_asrc[(size_t)s * 8 + h] + adv;
            al = al > 0.f ? al : NEG_SLOPE * al;
            float ex = v ? __expf(al) : 0.f;
            den += ex;
            int nval = min(end - base, 4);
            for (int j = 0; j < nval; j++) {
                int sl = j * 8;
                int sj = __shfl_sync(FULL, s, sl);
                float e0 = __shfl_sync(FULL, ex, sl + (lane >> 3));
                float e1 = __shfl_sync(FULL, ex, sl + (lane >> 3) + 4);
                acc0 = fmaf(g_xw[(size_t)sj * 64 + lane], e0, acc0);
                acc1 = fmaf(g_xw[(size_t)sj * 64 + 32 + lane], e1, acc1);
            }
        }
        den += __shfl_xor_sync(FULL, den, 8);
        den += __shfl_xor_sync(FULL, den, 16);
        float d0 = __shfl_sync(FULL, den, lane >> 3);
        float d1 = __shfl_sync(FULL, den, (lane >> 3) + 4);
        g_conv[(size_t)wid * 64 + lane]      = acc0 / d0 + __ldg(&bias[lane]);
        g_conv[(size_t)wid * 64 + 32 + lane] = acc1 / d1 + __ldg(&bias[lane + 32]);
    } else {
        float ad = g_adst[wid];
        float den = 0.f;
        for (int base = beg; base < end; base += 32) {
            int e = base + lane;
            bool v = e < end;
            int s = v ? g_esrc[e] : 0;
            float al = g_asrc[s] + ad;
            al = al > 0.f ? al : NEG_SLOPE * al;
            float ex = v ? __expf(al) : 0.f;
            den += ex;
            int nval = min(end - base, 32);
            for (int j = 0; j < nval; j++) {
                int sj = __shfl_sync(FULL, s, j);
                float ej = __shfl_sync(FULL, ex, j);
                acc0 = fmaf(g_xw[(size_t)sj * 64 + lane], ej, acc0);
                acc1 = fmaf(g_xw[(size_t)sj * 64 + 32 + lane], ej, acc1);
            }
        }
        #pragma unroll
        for (int o = 16; o; o >>= 1) den += __shfl_xor_sync(FULL, den, o);
        g_conv[(size_t)wid * 64 + lane]      = acc0 / den + __ldg(&bias[lane]);
        g_conv[(size_t)wid * 64 + 32 + lane] = acc1 / den + __ldg(&bias[lane + 32]);
    }
}

// ---------------- post: h_next = elu(bn(conv) + identity) ----------------
__global__ void post_kernel(int which,
                            const float* __restrict__ bg, const float* __restrict__ bb,
                            const float* __restrict__ bm, const float* __restrict__ bv)
{
    const float* ident = which == 0 ? g_h0 : g_h1;
    float* outb        = which == 0 ? g_h1 : g_h2;
    int idx = blockIdx.x * blockDim.x + threadIdx.x;  // float4 index
    if (idx >= N_NODES * 16) return;
    float4 c = ((const float4*)g_conv)[idx];
    float4 id = ((const float4*)ident)[idx];
    int cb = (idx & 15) * 4;
    float cv[4] = {c.x, c.y, c.z, c.w};
    float iv[4] = {id.x, id.y, id.z, id.w};
    float ov[4];
    #pragma unroll
    for (int k = 0; k < 4; k++) {
        float s = __ldg(&bg[cb + k]) * rsqrtf(__ldg(&bv[cb + k]) + BN_EPS);
        float v = cv[k] * s + (__ldg(&bb[cb + k]) - __ldg(&bm[cb + k]) * s) + iv[k];
        ov[k] = v > 0.f ? v : expm1f(v);
    }
    ((float4*)outb)[idx] = make_float4(ov[0], ov[1], ov[2], ov[3]);
}

// ---------------- classifier: out = h2 @ cls_W + cls_b ----------------
__global__ __launch_bounds__(256) void cls_kernel(
    const float* __restrict__ clsW, const float* __restrict__ clsB,
    float* __restrict__ out)
{
    __shared__ float Ws[64 * 8];
    __shared__ float Hs[32][65];
    int tid = threadIdx.x;
    int nb = blockIdx.x * 32;
    for (int i = tid; i < 512; i += 256) Ws[i] = clsW[i];
    for (int i = tid; i < 32 * 64; i += 256) {
        int r = i >> 6, c = i & 63;
        int node = nb + r;
        Hs[r][c] = (node < N_NODES) ? g_h2[(size_t)node * 64 + c] : 0.f;
    }
    __syncthreads();
    int nl = tid >> 3, o = tid & 7;
    int node = nb + nl;
    if (node < N_NODES) {
        float s = 0.f;
        #pragma unroll 8
        for (int c = 0; c < 64; c++)
            s = fmaf(Hs[nl][c], Ws[c * 8 + o], s);
        out[(size_t)node * 8 + o] = s + __ldg(&clsB[o]);
    }
}

// ---------------- launch ----------------
extern "C" void kernel_launch(void* const* d_in, const int* in_sizes, int n_in,
                              void* d_out, int out_size)
{
    const float *x, *projW, *projB;
    const int* ei;
    const float *bn1g, *bn1b, *bn1m, *bn1v;
    const float *bn2g, *bn2b, *bn2m, *bn2v;
    const float *bn3g, *bn3b, *bn3m, *bn3v;
    const float *W1, *as1, *ad1, *b1;
    const float *W2, *as2, *ad2, *b2;
    const float *clsW, *clsB;

    x     = (const float*)d_in[0];
    ei    = (const int*)d_in[1];
    projW = (const float*)d_in[2];
    projB = (const float*)d_in[3];
    bn1g = (const float*)d_in[4]; bn1b = (const float*)d_in[5];
    bn1m = (const float*)d_in[6]; bn1v = (const float*)d_in[7];

    if (in_sizes[8] == 4096) {
        // reference() signature order
        W1  = (const float*)d_in[8];
        as1 = (const float*)d_in[9];
        ad1 = (const float*)d_in[10];
        b1  = (const float*)d_in[11];
        bn2g = (const float*)d_in[12]; bn2b = (const float*)d_in[13];
        bn2m = (const float*)d_in[14]; bn2v = (const float*)d_in[15];
        W2  = (const float*)d_in[16];
        as2 = (const float*)d_in[17];
        ad2 = (const float*)d_in[18];
        b2  = (const float*)d_in[19];
        bn3g = (const float*)d_in[20]; bn3b = (const float*)d_in[21];
        bn3m = (const float*)d_in[22]; bn3v = (const float*)d_in[23];
        clsW = (const float*)d_in[24];
        clsB = (const float*)d_in[25];
    } else {
        // setup_inputs() dict order
        bn2g = (const float*)d_in[8];  bn2b = (const float*)d_in[9];
        bn2m = (const float*)d_in[10]; bn2v = (const float*)d_in[11];
        bn3g = (const float*)d_in[12]; bn3b = (const float*)d_in[13];
        bn3m = (const float*)d_in[14]; bn3v = (const float*)d_in[15];
        W1  = (const float*)d_in[16];
        as1 = (const float*)d_in[17];
        ad1 = (const float*)d_in[18];
        b1  = (const float*)d_in[19];
        W2  = (const float*)d_in[20];
        as2 = (const float*)d_in[21];
        ad2 = (const float*)d_in[22];
        b2  = (const float*)d_in[23];
        clsW = (const float*)d_in[24];
        clsB = (const float*)d_in[25];
    }
    float* out = (float*)d_out;

    // CSR build (zero kernel folded into count/scatter)
    count_kernel<<<(TOT_E + 1023) / 1024, 1024>>>(ei);
    scanA_kernel<<<SCAN_BLOCKS, 1024>>>();
    scanB_kernel<<<1, 1>>>();
    scanC_kernel<<<SCAN_BLOCKS, 1024>>>();
    scatter_kernel<<<(TOT_E + 1023) / 1024, 1024>>>(ei);

    // projection + BN1 + ELU -> g_h0 (double-buffered)
    proj_kernel<<<(N_NODES + 127) / 128, 256>>>(x, projW, projB, bn1g, bn1b, bn1m, bn1v);

    // GAT conv 1 (H=8)
    xw64_kernel<<<(N_NODES + 63) / 64, 256>>>(0, W1);
    att_kernel<8><<<(N_NODES * 8 + 255) / 256, 256>>>(as1, ad1);
    gather_kernel<8><<<(N_NODES * 32 + 255) / 256, 256>>>(b1);
    post_kernel<<<(N_NODES * 16 + 255) / 256, 256>>>(0, bn2g, bn2b, bn2m, bn2v);

    // GAT conv 2 (H=1)
    xw64_kernel<<<(N_NODES + 63) / 64, 256>>>(1, W2);
    att_kernel<1><<<(N_NODES + 255) / 256, 256>>>(as2, ad2);
    gather_kernel<1><<<(N_NODES * 32 + 255) / 256, 256>>>(b2);
    post_kernel<<<(N_NODES * 16 + 255) / 256, 256>>>(1, bn3g, bn3b, bn3m, bn3v);

    // classifier
    cls_kernel<<<(N_NODES + 31) / 32, 256>>>(clsW, clsB, out);
}

// round 15
// speedup vs baseline: 1.1105x; 1.1105x over previous
#include <cuda_runtime.h>
#include <math.h>
#include <stdint.h>

#define N_NODES 50000
#define E_EDGES 800000
#define TOT_E   (E_EDGES + N_NODES)
#define IN_C    768
#define HID     64
#define OUT_C   8
#define BN_EPS  1e-5f
#define NEG_SLOPE 0.2f
#define FULL    0xffffffffu

// ---------------- scratch (device globals: no allocation allowed) ----------
__device__ float g_h0[N_NODES * HID];   // post proj+bn1+elu (identity 1)
__device__ float g_xw[N_NODES * HID];   // per-conv transformed features
__device__ float g_asrc[N_NODES * 8];
__device__ float g_adst[N_NODES * 8];
__device__ float g_conv[N_NODES * HID]; // conv output (incl. bias)
__device__ float g_h1[N_NODES * HID];
__device__ float g_h2[N_NODES * HID];

__device__ int g_cnt[N_NODES];          // zeroed by scatter for next call
__device__ int g_cur[N_NODES];          // zeroed by count at start of call
__device__ int g_off[N_NODES + 1];
__device__ int g_esrc[TOT_E];

#define SCAN_BLOCKS 49   // ceil(50000/1024)
__device__ int g_blksum[SCAN_BLOCKS];

// ---------------- CSR build ----------------
__global__ void count_kernel(const int* __restrict__ ei) {
    int e = blockIdx.x * blockDim.x + threadIdx.x;
    if (e < N_NODES) g_cur[e] = 0;
    if (e >= TOT_E) return;
    int d = (e < E_EDGES) ? ei[E_EDGES + e] : (e - E_EDGES);
    atomicAdd(&g_cnt[d], 1);
}

__global__ void scanA_kernel() {
    __shared__ int sm[32];
    int tid = threadIdx.x;
    int idx = blockIdx.x * 1024 + tid;
    int v = (idx < N_NODES) ? g_cnt[idx] : 0;
    #pragma unroll
    for (int o = 16; o; o >>= 1) v += __shfl_xor_sync(FULL, v, o);
    if ((tid & 31) == 0) sm[tid >> 5] = v;
    __syncthreads();
    if (tid < 32) {
        int t = sm[tid];
        #pragma unroll
        for (int o = 16; o; o >>= 1) t += __shfl_xor_sync(FULL, t, o);
        if (tid == 0) g_blksum[blockIdx.x] = t;
    }
}

__global__ void scanB_kernel() {
    int run = 0;
    for (int b = 0; b < SCAN_BLOCKS; b++) {
        int t = g_blksum[b];
        g_blksum[b] = run;
        run += t;
    }
    g_off[N_NODES] = TOT_E;
}

__global__ void scanC_kernel() {
    __shared__ int warpsum[32];
    int tid = threadIdx.x;
    int idx = blockIdx.x * 1024 + tid;
    int v = (idx < N_NODES) ? g_cnt[idx] : 0;
    int x = v;
    #pragma unroll
    for (int o = 1; o < 32; o <<= 1) {
        int t = __shfl_up_sync(FULL, x, o);
        if ((tid & 31) >= o) x += t;
    }
    if ((tid & 31) == 31) warpsum[tid >> 5] = x;
    __syncthreads();
    if (tid < 32) {
        int w = warpsum[tid];
        int s = w;
        #pragma unroll
        for (int o = 1; o < 32; o <<= 1) {
            int t = __shfl_up_sync(FULL, s, o);
            if (tid >= o) s += t;
        }
        warpsum[tid] = s - w;   // exclusive warp base
    }
    __syncthreads();
    int excl = (x - v) + warpsum[tid >> 5] + g_blksum[blockIdx.x];
    if (idx < N_NODES) g_off[idx] = excl;
}

__global__ void scatter_kernel(const int* __restrict__ ei) {
    int e = blockIdx.x * blockDim.x + threadIdx.x;
    if (e < N_NODES) g_cnt[e] = 0;   // reset for next call
    if (e >= TOT_E) return;
    int s, d;
    if (e < E_EDGES) { s = ei[e]; d = ei[E_EDGES + e]; }
    else { s = e - E_EDGES; d = s; }
    int pos = g_off[d] + atomicAdd(&g_cur[d], 1);
    g_esrc[pos] = s;
}

// ---------------- projection GEMM (x @ proj_W + b) -> BN1 -> ELU ----------
// Inner loop uses packed fma.rn.f32x2 (sm_100+ baseline PTX): accumulators
// hold row-pairs, A row-pairs loaded as single 64-bit smem loads.
__global__ __launch_bounds__(256) void proj_kernel(
    const float* __restrict__ x, const float* __restrict__ W,
    const float* __restrict__ pb,
    const float* __restrict__ bg, const float* __restrict__ bb,
    const float* __restrict__ bm, const float* __restrict__ bv)
{
    __shared__ float As[16][132];  // [k][m], padded (row stride 528B, 8B-aligned)
    __shared__ float Bs[16][64];   // [k][n]
    int tid = threadIdx.x;
    int tx = tid & 15, ty = tid >> 4;
    int row0 = blockIdx.x * 128;

    // acc2[p][j]: packed rows (ty*8+2p, ty*8+2p+1), col tx*4+j
    unsigned long long acc2[4][4];
    #pragma unroll
    for (int p = 0; p < 4; p++)
        #pragma unroll
        for (int j = 0; j < 4; j++) acc2[p][j] = 0ull;

    for (int k0 = 0; k0 < IN_C; k0 += 16) {
        #pragma unroll
        for (int l = 0; l < 2; l++) {
            int idx = tid + l * 256;
            int r = idx >> 2, c4 = idx & 3;
            int grow = row0 + r;
            float4 av = make_float4(0.f, 0.f, 0.f, 0.f);
            if (grow < N_NODES)
                av = *(const float4*)&x[(size_t)grow * IN_C + k0 + c4 * 4];
            As[c4 * 4 + 0][r] = av.x;
            As[c4 * 4 + 1][r] = av.y;
            As[c4 * 4 + 2][r] = av.z;
            As[c4 * 4 + 3][r] = av.w;
        }
        {
            int k = tid >> 4, c4 = tid & 15;
            *(float4*)&Bs[k][c4 * 4] = *(const float4*)&W[(k0 + k) * 64 + c4 * 4];
        }
        __syncthreads();
        #pragma unroll
        for (int k = 0; k < 16; k++) {
            // A row-pairs: contiguous in smem -> 64-bit loads
            unsigned long long a01 = *(const unsigned long long*)&As[k][ty * 8 + 0];
            unsigned long long a23 = *(const unsigned long long*)&As[k][ty * 8 + 2];
            unsigned long long a45 = *(const unsigned long long*)&As[k][ty * 8 + 4];
            unsigned long long a67 = *(const unsigned long long*)&As[k][ty * 8 + 6];
            float4 b = *(float4*)&Bs[k][tx * 4];
            unsigned long long bd0, bd1, bd2, bd3;
            asm("mov.b64 %0, {%1, %1};" : "=l"(bd0) : "f"(b.x));
            asm("mov.b64 %0, {%1, %1};" : "=l"(bd1) : "f"(b.y));
            asm("mov.b64 %0, {%1, %1};" : "=l"(bd2) : "f"(b.z));
            asm("mov.b64 %0, {%1, %1};" : "=l"(bd3) : "f"(b.w));
            unsigned long long ap[4] = {a01, a23, a45, a67};
            unsigned long long bp[4] = {bd0, bd1, bd2, bd3};
            #pragma unroll
            for (int p = 0; p < 4; p++)
                #pragma unroll
                for (int j = 0; j < 4; j++)
                    asm("fma.rn.f32x2 %0, %1, %2, %0;"
                        : "+l"(acc2[p][j]) : "l"(ap[p]), "l"(bp[j]));
        }
        __syncthreads();
    }

    // unpack accumulators
    float accf[8][4];
    #pragma unroll
    for (int p = 0; p < 4; p++)
        #pragma unroll
        for (int j = 0; j < 4; j++) {
            float lo, hi;
            asm("mov.b64 {%0, %1}, %2;" : "=f"(lo), "=f"(hi) : "l"(acc2[p][j]));
            accf[2 * p][j] = lo;
            accf[2 * p + 1][j] = hi;
        }

    float sc[4], sh[4], pbv[4];
    #pragma unroll
    for (int j = 0; j < 4; j++) {
        int col = tx * 4 + j;
        float s = bg[col] * rsqrtf(bv[col] + BN_EPS);
        sc[j] = s;
        sh[j] = bb[col] - bm[col] * s;
        pbv[j] = pb[col];
    }
    #pragma unroll
    for (int i = 0; i < 8; i++) {
        int grow = row0 + ty * 8 + i;
        if (grow < N_NODES) {
            float vj[4];
            #pragma unroll
            for (int j = 0; j < 4; j++) {
                float v = (accf[i][j] + pbv[j]) * sc[j] + sh[j];
                vj[j] = v > 0.f ? v : expm1f(v);
            }
            *(float4*)&g_h0[(size_t)grow * 64 + tx * 4] =
                make_float4(vj[0], vj[1], vj[2], vj[3]);
        }
    }
}

// ---------------- 64x64 feature transform: g_xw = hin @ W ----------------
__global__ __launch_bounds__(256) void xw64_kernel(int which_in,
                                                   const float* __restrict__ W)
{
    const float* hin = which_in == 0 ? g_h0 : g_h1;
    __shared__ float Hs[64][65];
    __shared__ float Ws[64][64];
    int tid = threadIdx.x;
    int row0 = blockIdx.x * 64;

    for (int i = tid; i < 64 * 64; i += 256) {
        int r = i >> 6, c = i & 63;
        Ws[r][c] = W[i];
        int node = row0 + r;
        Hs[r][c] = (node < N_NODES) ? hin[(size_t)node * 64 + c] : 0.f;
    }
    __syncthreads();

    int r = tid >> 2, q = tid & 3;
    float acc[16];
    #pragma unroll
    for (int j = 0; j < 16; j++) acc[j] = 0.f;

    #pragma unroll 8
    for (int k = 0; k < 64; k++) {
        float hv = Hs[r][k];
        #pragma unroll
        for (int j = 0; j < 4; j++) {
            float4 w = *(float4*)&Ws[k][q * 16 + j * 4];
            acc[j * 4 + 0] = fmaf(hv, w.x, acc[j * 4 + 0]);
            acc[j * 4 + 1] = fmaf(hv, w.y, acc[j * 4 + 1]);
            acc[j * 4 + 2] = fmaf(hv, w.z, acc[j * 4 + 2]);
            acc[j * 4 + 3] = fmaf(hv, w.w, acc[j * 4 + 3]);
        }
    }
    int node = row0 + r;
    if (node < N_NODES) {
        #pragma unroll
        for (int j = 0; j < 4; j++)
            *(float4*)&g_xw[(size_t)node * 64 + q * 16 + j * 4] =
                make_float4(acc[j * 4], acc[j * 4 + 1], acc[j * 4 + 2], acc[j * 4 + 3]);
    }
}

// ---------------- attention coefficients ----------------
template <int H>
__global__ void att_kernel(const float* __restrict__ att_s,
                           const float* __restrict__ att_d)
{
    const int C = 64 / H;
    int t = blockIdx.x * blockDim.x + threadIdx.x;
    if (t >= N_NODES * H) return;
    int n = t / H, h = t % H;
    const float* row = &g_xw[(size_t)n * 64 + h * C];
    float ss = 0.f, sd = 0.f;
    #pragma unroll
    for (int c = 0; c < C; c++) {
        float v = row[c];
        ss = fmaf(v, __ldg(&att_s[h * C + c]), ss);
        sd = fmaf(v, __ldg(&att_d[h * C + c]), sd);
    }
    g_asrc[t] = ss;
    g_adst[t] = sd;
}

// ---- GAT gather: one warp per destination node (single pass, no-max softmax) ----
template <int H>
__global__ void gather_kernel(const float* __restrict__ bias)
{
    int wid = (blockIdx.x * blockDim.x + threadIdx.x) >> 5;
    if (wid >= N_NODES) return;
    int lane = threadIdx.x & 31;
    int beg = g_off[wid], end = g_off[wid + 1];

    float acc0 = 0.f, acc1 = 0.f;

    if (H == 8) {
        int sub = lane >> 3, h = lane & 7;
        float ad = (lane < 8) ? g_adst[(size_t)wid * 8 + lane] : 0.f;
        float adv = __shfl_sync(FULL, ad, h);

        float den = 0.f;
        for (int base = beg; base < end; base += 4) {
            int e = base + sub;
            bool v = e < end;
            int s = v ? g_esrc[e] : 0;
            float al = g_asrc[(size_t)s * 8 + h] + adv;
            al = al > 0.f ? al : NEG_SLOPE * al;
            float ex = v ? __expf(al) : 0.f;
            den += ex;
            int nval = min(end - base, 4);
            for (int j = 0; j < nval; j++) {
                int sl = j * 8;
                int sj = __shfl_sync(FULL, s, sl);
                float e0 = __shfl_sync(FULL, ex, sl + (lane >> 3));
                float e1 = __shfl_sync(FULL, ex, sl + (lane >> 3) + 4);
                acc0 = fmaf(g_xw[(size_t)sj * 64 + lane], e0, acc0);
                acc1 = fmaf(g_xw[(size_t)sj * 64 + 32 + lane], e1, acc1);
            }
        }
        den += __shfl_xor_sync(FULL, den, 8);
        den += __shfl_xor_sync(FULL, den, 16);
        float d0 = __shfl_sync(FULL, den, lane >> 3);
        float d1 = __shfl_sync(FULL, den, (lane >> 3) + 4);
        g_conv[(size_t)wid * 64 + lane]      = acc0 / d0 + __ldg(&bias[lane]);
        g_conv[(size_t)wid * 64 + 32 + lane] = acc1 / d1 + __ldg(&bias[lane + 32]);
    } else {
        float ad = g_adst[wid];
        float den = 0.f;
        for (int base = beg; base < end; base += 32) {
            int e = base + lane;
            bool v = e < end;
            int s = v ? g_esrc[e] : 0;
            float al = g_asrc[s] + ad;
            al = al > 0.f ? al : NEG_SLOPE * al;
            float ex = v ? __expf(al) : 0.f;
            den += ex;
            int nval = min(end - base, 32);
            for (int j = 0; j < nval; j++) {
                int sj = __shfl_sync(FULL, s, j);
                float ej = __shfl_sync(FULL, ex, j);
                acc0 = fmaf(g_xw[(size_t)sj * 64 + lane], ej, acc0);
                acc1 = fmaf(g_xw[(size_t)sj * 64 + 32 + lane], ej, acc1);
            }
        }
        #pragma unroll
        for (int o = 16; o; o >>= 1) den += __shfl_xor_sync(FULL, den, o);
        g_conv[(size_t)wid * 64 + lane]      = acc0 / den + __ldg(&bias[lane]);
        g_conv[(size_t)wid * 64 + 32 + lane] = acc1 / den + __ldg(&bias[lane + 32]);
    }
}

// ---------------- post: h_next = elu(bn(conv) + identity) ----------------
__global__ void post_kernel(int which,
                            const float* __restrict__ bg, const float* __restrict__ bb,
                            const float* __restrict__ bm, const float* __restrict__ bv)
{
    const float* ident = which == 0 ? g_h0 : g_h1;
    float* outb        = which == 0 ? g_h1 : g_h2;
    int idx = blockIdx.x * blockDim.x + threadIdx.x;  // float4 index
    if (idx >= N_NODES * 16) return;
    float4 c = ((const float4*)g_conv)[idx];
    float4 id = ((const float4*)ident)[idx];
    int cb = (idx & 15) * 4;
    float cv[4] = {c.x, c.y, c.z, c.w};
    float iv[4] = {id.x, id.y, id.z, id.w};
    float ov[4];
    #pragma unroll
    for (int k = 0; k < 4; k++) {
        float s = __ldg(&bg[cb + k]) * rsqrtf(__ldg(&bv[cb + k]) + BN_EPS);
        float v = cv[k] * s + (__ldg(&bb[cb + k]) - __ldg(&bm[cb + k]) * s) + iv[k];
        ov[k] = v > 0.f ? v : expm1f(v);
    }
    ((float4*)outb)[idx] = make_float4(ov[0], ov[1], ov[2], ov[3]);
}

// ---------------- classifier: out = h2 @ cls_W + cls_b ----------------
__global__ __launch_bounds__(256) void cls_kernel(
    const float* __restrict__ clsW, const float* __restrict__ clsB,
    float* __restrict__ out)
{
    __shared__ float Ws[64 * 8];
    __shared__ float Hs[32][65];
    int tid = threadIdx.x;
    int nb = blockIdx.x * 32;
    for (int i = tid; i < 512; i += 256) Ws[i] = clsW[i];
    for (int i = tid; i < 32 * 64; i += 256) {
        int r = i >> 6, c = i & 63;
        int node = nb + r;
        Hs[r][c] = (node < N_NODES) ? g_h2[(size_t)node * 64 + c] : 0.f;
    }
    __syncthreads();
    int nl = tid >> 3, o = tid & 7;
    int node = nb + nl;
    if (node < N_NODES) {
        float s = 0.f;
        #pragma unroll 8
        for (int c = 0; c < 64; c++)
            s = fmaf(Hs[nl][c], Ws[c * 8 + o], s);
        out[(size_t)node * 8 + o] = s + __ldg(&clsB[o]);
    }
}

// ---------------- launch ----------------
extern "C" void kernel_launch(void* const* d_in, const int* in_sizes, int n_in,
                              void* d_out, int out_size)
{
    const float *x, *projW, *projB;
    const int* ei;
    const float *bn1g, *bn1b, *bn1m, *bn1v;
    const float *bn2g, *bn2b, *bn2m, *bn2v;
    const float *bn3g, *bn3b, *bn3m, *bn3v;
    const float *W1, *as1, *ad1, *b1;
    const float *W2, *as2, *ad2, *b2;
    const float *clsW, *clsB;

    x     = (const float*)d_in[0];
    ei    = (const int*)d_in[1];
    projW = (const float*)d_in[2];
    projB = (const float*)d_in[3];
    bn1g = (const float*)d_in[4]; bn1b = (const float*)d_in[5];
    bn1m = (const float*)d_in[6]; bn1v = (const float*)d_in[7];

    if (in_sizes[8] == 4096) {
        // reference() signature order
        W1  = (const float*)d_in[8];
        as1 = (const float*)d_in[9];
        ad1 = (const float*)d_in[10];
        b1  = (const float*)d_in[11];
        bn2g = (const float*)d_in[12]; bn2b = (const float*)d_in[13];
        bn2m = (const float*)d_in[14]; bn2v = (const float*)d_in[15];
        W2  = (const float*)d_in[16];
        as2 = (const float*)d_in[17];
        ad2 = (const float*)d_in[18];
        b2  = (const float*)d_in[19];
        bn3g = (const float*)d_in[20]; bn3b = (const float*)d_in[21];
        bn3m = (const float*)d_in[22]; bn3v = (const float*)d_in[23];
        clsW = (const float*)d_in[24];
        clsB = (const float*)d_in[25];
    } else {
        // setup_inputs() dict order
        bn2g = (const float*)d_in[8];  bn2b = (const float*)d_in[9];
        bn2m = (const float*)d_in[10]; bn2v = (const float*)d_in[11];
        bn3g = (const float*)d_in[12]; bn3b = (const float*)d_in[13];
        bn3m = (const float*)d_in[14]; bn3v = (const float*)d_in[15];
        W1  = (const float*)d_in[16];
        as1 = (const float*)d_in[17];
        ad1 = (const float*)d_in[18];
        b1  = (const float*)d_in[19];
        W2  = (const float*)d_in[20];
        as2 = (const float*)d_in[21];
        ad2 = (const float*)d_in[22];
        b2  = (const float*)d_in[23];
        clsW = (const float*)d_in[24];
        clsB = (const float*)d_in[25];
    }
    float* out = (float*)d_out;

    // CSR build (zero kernel folded into count/scatter)
    count_kernel<<<(TOT_E + 1023) / 1024, 1024>>>(ei);
    scanA_kernel<<<SCAN_BLOCKS, 1024>>>();
    scanB_kernel<<<1, 1>>>();
    scanC_kernel<<<SCAN_BLOCKS, 1024>>>();
    scatter_kernel<<<(TOT_E + 1023) / 1024, 1024>>>(ei);

    // projection + BN1 + ELU -> g_h0 (f32x2 packed FMA)
    proj_kernel<<<(N_NODES + 127) / 128, 256>>>(x, projW, projB, bn1g, bn1b, bn1m, bn1v);

    // GAT conv 1 (H=8)
    xw64_kernel<<<(N_NODES + 63) / 64, 256>>>(0, W1);
    att_kernel<8><<<(N_NODES * 8 + 255) / 256, 256>>>(as1, ad1);
    gather_kernel<8><<<(N_NODES * 32 + 255) / 256, 256>>>(b1);
    post_kernel<<<(N_NODES * 16 + 255) / 256, 256>>>(0, bn2g, bn2b, bn2m, bn2v);

    // GAT conv 2 (H=1)
    xw64_kernel<<<(N_NODES + 63) / 64, 256>>>(1, W2);
    att_kernel<1><<<(N_NODES + 255) / 256, 256>>>(as2, ad2);
    gather_kernel<1><<<(N_NODES * 32 + 255) / 256, 256>>>(b2);
    post_kernel<<<(N_NODES * 16 + 255) / 256, 256>>>(1, bn3g, bn3b, bn3m, bn3v);

    // classifier
    cls_kernel<<<(N_NODES + 31) / 32, 256>>>(clsW, clsB, out);
}

// round 16
// speedup vs baseline: 1.1675x; 1.0513x over previous
#include <cuda_runtime.h>
#include <math.h>
#include <stdint.h>

#define N_NODES 50000
#define E_EDGES 800000
#define TOT_E   (E_EDGES + N_NODES)
#define IN_C    768
#define HID     64
#define OUT_C   8
#define BN_EPS  1e-5f
#define NEG_SLOPE 0.2f
#define FULL    0xffffffffu

// ---------------- scratch (device globals: no allocation allowed) ----------
__device__ float g_h0[N_NODES * HID];   // post proj+bn1+elu (identity 1)
__device__ float g_xw[N_NODES * HID];   // per-conv transformed features
__device__ float g_asrc[N_NODES * 8];
__device__ float g_adst[N_NODES * 8];
__device__ float g_conv[N_NODES * HID]; // conv output (incl. bias)
__device__ float g_h1[N_NODES * HID];
__device__ float g_h2[N_NODES * HID];

__device__ int g_cnt[N_NODES];          // zeroed by scatter for next call
__device__ int g_cur[N_NODES];          // zeroed by count at start of call
__device__ int g_off[N_NODES + 1];
__device__ int g_esrc[TOT_E];

#define SCAN_BLOCKS 49   // ceil(50000/1024)
__device__ int g_blksum[SCAN_BLOCKS];

// ---------------- CSR build ----------------
__global__ void count_kernel(const int* __restrict__ ei) {
    int e = blockIdx.x * blockDim.x + threadIdx.x;
    if (e < N_NODES) g_cur[e] = 0;
    if (e >= TOT_E) return;
    int d = (e < E_EDGES) ? ei[E_EDGES + e] : (e - E_EDGES);
    atomicAdd(&g_cnt[d], 1);
}

__global__ void scanA_kernel() {
    __shared__ int sm[32];
    int tid = threadIdx.x;
    int idx = blockIdx.x * 1024 + tid;
    int v = (idx < N_NODES) ? g_cnt[idx] : 0;
    #pragma unroll
    for (int o = 16; o; o >>= 1) v += __shfl_xor_sync(FULL, v, o);
    if ((tid & 31) == 0) sm[tid >> 5] = v;
    __syncthreads();
    if (tid < 32) {
        int t = sm[tid];
        #pragma unroll
        for (int o = 16; o; o >>= 1) t += __shfl_xor_sync(FULL, t, o);
        if (tid == 0) g_blksum[blockIdx.x] = t;
    }
}

__global__ void scanB_kernel() {
    int run = 0;
    for (int b = 0; b < SCAN_BLOCKS; b++) {
        int t = g_blksum[b];
        g_blksum[b] = run;
        run += t;
    }
    g_off[N_NODES] = TOT_E;
}

__global__ void scanC_kernel() {
    __shared__ int warpsum[32];
    int tid = threadIdx.x;
    int idx = blockIdx.x * 1024 + tid;
    int v = (idx < N_NODES) ? g_cnt[idx] : 0;
    int x = v;
    #pragma unroll
    for (int o = 1; o < 32; o <<= 1) {
        int t = __shfl_up_sync(FULL, x, o);
        if ((tid & 31) >= o) x += t;
    }
    if ((tid & 31) == 31) warpsum[tid >> 5] = x;
    __syncthreads();
    if (tid < 32) {
        int w = warpsum[tid];
        int s = w;
        #pragma unroll
        for (int o = 1; o < 32; o <<= 1) {
            int t = __shfl_up_sync(FULL, s, o);
            if (tid >= o) s += t;
        }
        warpsum[tid] = s - w;   // exclusive warp base
    }
    __syncthreads();
    int excl = (x - v) + warpsum[tid >> 5] + g_blksum[blockIdx.x];
    if (idx < N_NODES) g_off[idx] = excl;
}

__global__ void scatter_kernel(const int* __restrict__ ei) {
    int e = blockIdx.x * blockDim.x + threadIdx.x;
    if (e < N_NODES) g_cnt[e] = 0;   // reset for next call
    if (e >= TOT_E) return;
    int s, d;
    if (e < E_EDGES) { s = ei[e]; d = ei[E_EDGES + e]; }
    else { s = e - E_EDGES; d = s; }
    int pos = g_off[d] + atomicAdd(&g_cur[d], 1);
    g_esrc[pos] = s;
}

// ---------------- projection GEMM (x @ proj_W + b) -> BN1 -> ELU ----------
// Inner loop uses packed fma.rn.f32x2; accumulators hold row-pairs.
__global__ __launch_bounds__(256) void proj_kernel(
    const float* __restrict__ x, const float* __restrict__ W,
    const float* __restrict__ pb,
    const float* __restrict__ bg, const float* __restrict__ bb,
    const float* __restrict__ bm, const float* __restrict__ bv)
{
    __shared__ float As[16][132];  // [k][m], padded
    __shared__ float Bs[16][64];   // [k][n]
    int tid = threadIdx.x;
    int tx = tid & 15, ty = tid >> 4;
    int row0 = blockIdx.x * 128;

    unsigned long long acc2[4][4];
    #pragma unroll
    for (int p = 0; p < 4; p++)
        #pragma unroll
        for (int j = 0; j < 4; j++) acc2[p][j] = 0ull;

    for (int k0 = 0; k0 < IN_C; k0 += 16) {
        #pragma unroll
        for (int l = 0; l < 2; l++) {
            int idx = tid + l * 256;
            int r = idx >> 2, c4 = idx & 3;
            int grow = row0 + r;
            float4 av = make_float4(0.f, 0.f, 0.f, 0.f);
            if (grow < N_NODES)
                av = *(const float4*)&x[(size_t)grow * IN_C + k0 + c4 * 4];
            As[c4 * 4 + 0][r] = av.x;
            As[c4 * 4 + 1][r] = av.y;
            As[c4 * 4 + 2][r] = av.z;
            As[c4 * 4 + 3][r] = av.w;
        }
        {
            int k = tid >> 4, c4 = tid & 15;
            *(float4*)&Bs[k][c4 * 4] = *(const float4*)&W[(k0 + k) * 64 + c4 * 4];
        }
        __syncthreads();
        #pragma unroll
        for (int k = 0; k < 16; k++) {
            unsigned long long a01 = *(const unsigned long long*)&As[k][ty * 8 + 0];
            unsigned long long a23 = *(const unsigned long long*)&As[k][ty * 8 + 2];
            unsigned long long a45 = *(const unsigned long long*)&As[k][ty * 8 + 4];
            unsigned long long a67 = *(const unsigned long long*)&As[k][ty * 8 + 6];
            float4 b = *(float4*)&Bs[k][tx * 4];
            unsigned long long bd0, bd1, bd2, bd3;
            asm("mov.b64 %0, {%1, %1};" : "=l"(bd0) : "f"(b.x));
            asm("mov.b64 %0, {%1, %1};" : "=l"(bd1) : "f"(b.y));
            asm("mov.b64 %0, {%1, %1};" : "=l"(bd2) : "f"(b.z));
            asm("mov.b64 %0, {%1, %1};" : "=l"(bd3) : "f"(b.w));
            unsigned long long ap[4] = {a01, a23, a45, a67};
            unsigned long long bp[4] = {bd0, bd1, bd2, bd3};
            #pragma unroll
            for (int p = 0; p < 4; p++)
                #pragma unroll
                for (int j = 0; j < 4; j++)
                    asm("fma.rn.f32x2 %0, %1, %2, %0;"
                        : "+l"(acc2[p][j]) : "l"(ap[p]), "l"(bp[j]));
        }
        __syncthreads();
    }

    float accf[8][4];
    #pragma unroll
    for (int p = 0; p < 4; p++)
        #pragma unroll
        for (int j = 0; j < 4; j++) {
            float lo, hi;
            asm("mov.b64 {%0, %1}, %2;" : "=f"(lo), "=f"(hi) : "l"(acc2[p][j]));
            accf[2 * p][j] = lo;
            accf[2 * p + 1][j] = hi;
        }

    float sc[4], sh[4], pbv[4];
    #pragma unroll
    for (int j = 0; j < 4; j++) {
        int col = tx * 4 + j;
        float s = bg[col] * rsqrtf(bv[col] + BN_EPS);
        sc[j] = s;
        sh[j] = bb[col] - bm[col] * s;
        pbv[j] = pb[col];
    }
    #pragma unroll
    for (int i = 0; i < 8; i++) {
        int grow = row0 + ty * 8 + i;
        if (grow < N_NODES) {
            float vj[4];
            #pragma unroll
            for (int j = 0; j < 4; j++) {
                float v = (accf[i][j] + pbv[j]) * sc[j] + sh[j];
                vj[j] = v > 0.f ? v : expm1f(v);
            }
            *(float4*)&g_h0[(size_t)grow * 64 + tx * 4] =
                make_float4(vj[0], vj[1], vj[2], vj[3]);
        }
    }
}

// ---------------- 64x64 feature transform: g_xw = hin @ W ----------------
__global__ __launch_bounds__(256) void xw64_kernel(int which_in,
                                                   const float* __restrict__ W)
{
    const float* hin = which_in == 0 ? g_h0 : g_h1;
    __shared__ float Hs[64][65];
    __shared__ float Ws[64][64];
    int tid = threadIdx.x;
    int row0 = blockIdx.x * 64;

    for (int i = tid; i < 64 * 64; i += 256) {
        int r = i >> 6, c = i & 63;
        Ws[r][c] = W[i];
        int node = row0 + r;
        Hs[r][c] = (node < N_NODES) ? hin[(size_t)node * 64 + c] : 0.f;
    }
    __syncthreads();

    int r = tid >> 2, q = tid & 3;
    float acc[16];
    #pragma unroll
    for (int j = 0; j < 16; j++) acc[j] = 0.f;

    #pragma unroll 8
    for (int k = 0; k < 64; k++) {
        float hv = Hs[r][k];
        #pragma unroll
        for (int j = 0; j < 4; j++) {
            float4 w = *(float4*)&Ws[k][q * 16 + j * 4];
            acc[j * 4 + 0] = fmaf(hv, w.x, acc[j * 4 + 0]);
            acc[j * 4 + 1] = fmaf(hv, w.y, acc[j * 4 + 1]);
            acc[j * 4 + 2] = fmaf(hv, w.z, acc[j * 4 + 2]);
            acc[j * 4 + 3] = fmaf(hv, w.w, acc[j * 4 + 3]);
        }
    }
    int node = row0 + r;
    if (node < N_NODES) {
        #pragma unroll
        for (int j = 0; j < 4; j++)
            *(float4*)&g_xw[(size_t)node * 64 + q * 16 + j * 4] =
                make_float4(acc[j * 4], acc[j * 4 + 1], acc[j * 4 + 2], acc[j * 4 + 3]);
    }
}

// ---------------- attention coefficients ----------------
template <int H>
__global__ void att_kernel(const float* __restrict__ att_s,
                           const float* __restrict__ att_d)
{
    const int C = 64 / H;
    int t = blockIdx.x * blockDim.x + threadIdx.x;
    if (t >= N_NODES * H) return;
    int n = t / H, h = t % H;
    const float* row = &g_xw[(size_t)n * 64 + h * C];
    float ss = 0.f, sd = 0.f;
    #pragma unroll
    for (int c = 0; c < C; c++) {
        float v = row[c];
        ss = fmaf(v, __ldg(&att_s[h * C + c]), ss);
        sd = fmaf(v, __ldg(&att_d[h * C + c]), sd);
    }
    g_asrc[t] = ss;
    g_adst[t] = sd;
}

// ---- GAT gather: one warp per destination node (single pass, no-max softmax) ----
template <int H>
__global__ void gather_kernel(const float* __restrict__ bias)
{
    int wid = (blockIdx.x * blockDim.x + threadIdx.x) >> 5;
    if (wid >= N_NODES) return;
    int lane = threadIdx.x & 31;
    int beg = g_off[wid], end = g_off[wid + 1];

    float acc0 = 0.f, acc1 = 0.f;

    if (H == 8) {
        int sub = lane >> 3, h = lane & 7;
        float ad = (lane < 8) ? g_adst[(size_t)wid * 8 + lane] : 0.f;
        float adv = __shfl_sync(FULL, ad, h);

        float den = 0.f;
        for (int base = beg; base < end; base += 4) {
            int e = base + sub;
            bool v = e < end;
            int s = v ? g_esrc[e] : 0;
            float al = g_asrc[(size_t)s * 8 + h] + adv;
            al = al > 0.f ? al : NEG_SLOPE * al;
            float ex = v ? __expf(al) : 0.f;
            den += ex;
            int nval = min(end - base, 4);
            for (int j = 0; j < nval; j++) {
                int sl = j * 8;
                int sj = __shfl_sync(FULL, s, sl);
                float e0 = __shfl_sync(FULL, ex, sl + (lane >> 3));
                float e1 = __shfl_sync(FULL, ex, sl + (lane >> 3) + 4);
                acc0 = fmaf(g_xw[(size_t)sj * 64 + lane], e0, acc0);
                acc1 = fmaf(g_xw[(size_t)sj * 64 + 32 + lane], e1, acc1);
            }
        }
        den += __shfl_xor_sync(FULL, den, 8);
        den += __shfl_xor_sync(FULL, den, 16);
        float d0 = __shfl_sync(FULL, den, lane >> 3);
        float d1 = __shfl_sync(FULL, den, (lane >> 3) + 4);
        g_conv[(size_t)wid * 64 + lane]      = acc0 / d0 + __ldg(&bias[lane]);
        g_conv[(size_t)wid * 64 + 32 + lane] = acc1 / d1 + __ldg(&bias[lane + 32]);
    } else {
        float ad = g_adst[wid];
        float den = 0.f;
        for (int base = beg; base < end; base += 32) {
            int e = base + lane;
            bool v = e < end;
            int s = v ? g_esrc[e] : 0;
            float al = g_asrc[s] + ad;
            al = al > 0.f ? al : NEG_SLOPE * al;
            float ex = v ? __expf(al) : 0.f;
            den += ex;
            int nval = min(end - base, 32);
            for (int j = 0; j < nval; j++) {
                int sj = __shfl_sync(FULL, s, j);
                float ej = __shfl_sync(FULL, ex, j);
                acc0 = fmaf(g_xw[(size_t)sj * 64 + lane], ej, acc0);
                acc1 = fmaf(g_xw[(size_t)sj * 64 + 32 + lane], ej, acc1);
            }
        }
        #pragma unroll
        for (int o = 16; o; o >>= 1) den += __shfl_xor_sync(FULL, den, o);
        g_conv[(size_t)wid * 64 + lane]      = acc0 / den + __ldg(&bias[lane]);
        g_conv[(size_t)wid * 64 + 32 + lane] = acc1 / den + __ldg(&bias[lane + 32]);
    }
}

// ---------------- post: h_next = elu(bn(conv) + identity) ----------------
__global__ void post_kernel(int which,
                            const float* __restrict__ bg, const float* __restrict__ bb,
                            const float* __restrict__ bm, const float* __restrict__ bv)
{
    const float* ident = which == 0 ? g_h0 : g_h1;
    float* outb        = which == 0 ? g_h1 : g_h2;
    int idx = blockIdx.x * blockDim.x + threadIdx.x;  // float4 index
    if (idx >= N_NODES * 16) return;
    float4 c = ((const float4*)g_conv)[idx];
    float4 id = ((const float4*)ident)[idx];
    int cb = (idx & 15) * 4;
    float cv[4] = {c.x, c.y, c.z, c.w};
    float iv[4] = {id.x, id.y, id.z, id.w};
    float ov[4];
    #pragma unroll
    for (int k = 0; k < 4; k++) {
        float s = __ldg(&bg[cb + k]) * rsqrtf(__ldg(&bv[cb + k]) + BN_EPS);
        float v = cv[k] * s + (__ldg(&bb[cb + k]) - __ldg(&bm[cb + k]) * s) + iv[k];
        ov[k] = v > 0.f ? v : expm1f(v);
    }
    ((float4*)outb)[idx] = make_float4(ov[0], ov[1], ov[2], ov[3]);
}

// ---------------- classifier: out = h2 @ cls_W + cls_b ----------------
__global__ __launch_bounds__(256) void cls_kernel(
    const float* __restrict__ clsW, const float* __restrict__ clsB,
    float* __restrict__ out)
{
    __shared__ float Ws[64 * 8];
    __shared__ float Hs[32][65];
    int tid = threadIdx.x;
    int nb = blockIdx.x * 32;
    for (int i = tid; i < 512; i += 256) Ws[i] = clsW[i];
    for (int i = tid; i < 32 * 64; i += 256) {
        int r = i >> 6, c = i & 63;
        int node = nb + r;
        Hs[r][c] = (node < N_NODES) ? g_h2[(size_t)node * 64 + c] : 0.f;
    }
    __syncthreads();
    int nl = tid >> 3, o = tid & 7;
    int node = nb + nl;
    if (node < N_NODES) {
        float s = 0.f;
        #pragma unroll 8
        for (int c = 0; c < 64; c++)
            s = fmaf(Hs[nl][c], Ws[c * 8 + o], s);
        out[(size_t)node * 8 + o] = s + __ldg(&clsB[o]);
    }
}

// ---------------- launch ----------------
extern "C" void kernel_launch(void* const* d_in, const int* in_sizes, int n_in,
                              void* d_out, int out_size)
{
    const float *x, *projW, *projB;
    const int* ei;
    const float *bn1g, *bn1b, *bn1m, *bn1v;
    const float *bn2g, *bn2b, *bn2m, *bn2v;
    const float *bn3g, *bn3b, *bn3m, *bn3v;
    const float *W1, *as1, *ad1, *b1;
    const float *W2, *as2, *ad2, *b2;
    const float *clsW, *clsB;

    x     = (const float*)d_in[0];
    ei    = (const int*)d_in[1];
    projW = (const float*)d_in[2];
    projB = (const float*)d_in[3];
    bn1g = (const float*)d_in[4]; bn1b = (const float*)d_in[5];
    bn1m = (const float*)d_in[6]; bn1v = (const float*)d_in[7];

    if (in_sizes[8] == 4096) {
        // reference() signature order
        W1  = (const float*)d_in[8];
        as1 = (const float*)d_in[9];
        ad1 = (const float*)d_in[10];
        b1  = (const float*)d_in[11];
        bn2g = (const float*)d_in[12]; bn2b = (const float*)d_in[13];
        bn2m = (const float*)d_in[14]; bn2v = (const float*)d_in[15];
        W2  = (const float*)d_in[16];
        as2 = (const float*)d_in[17];
        ad2 = (const float*)d_in[18];
        b2  = (const float*)d_in[19];
        bn3g = (const float*)d_in[20]; bn3b = (const float*)d_in[21];
        bn3m = (const float*)d_in[22]; bn3v = (const float*)d_in[23];
        clsW = (const float*)d_in[24];
        clsB = (const float*)d_in[25];
    } else {
        // setup_inputs() dict order
        bn2g = (const float*)d_in[8];  bn2b = (const float*)d_in[9];
        bn2m = (const float*)d_in[10]; bn2v = (const float*)d_in[11];
        bn3g = (const float*)d_in[12]; bn3b = (const float*)d_in[13];
        bn3m = (const float*)d_in[14]; bn3v = (const float*)d_in[15];
        W1  = (const float*)d_in[16];
        as1 = (const float*)d_in[17];
        ad1 = (const float*)d_in[18];
        b1  = (const float*)d_in[19];
        W2  = (const float*)d_in[20];
        as2 = (const float*)d_in[21];
        ad2 = (const float*)d_in[22];
        b2  = (const float*)d_in[23];
        clsW = (const float*)d_in[24];
        clsB = (const float*)d_in[25];
    }
    float* out = (float*)d_out;

    // ---- graph fork: CSR build on a side stream, concurrent with proj ----
    cudaStream_t s_csr;
    cudaStreamCreateWithFlags(&s_csr, cudaStreamNonBlocking);
    cudaEvent_t e_fork, e_join;
    cudaEventCreateWithFlags(&e_fork, cudaEventDisableTiming);
    cudaEventCreateWithFlags(&e_join, cudaEventDisableTiming);

    // fork from the (captured) legacy stream
    cudaEventRecord(e_fork, 0);
    cudaStreamWaitEvent(s_csr, e_fork, 0);

    // CSR chain on side stream
    count_kernel<<<(TOT_E + 1023) / 1024, 1024, 0, s_csr>>>(ei);
    scanA_kernel<<<SCAN_BLOCKS, 1024, 0, s_csr>>>();
    scanB_kernel<<<1, 1, 0, s_csr>>>();
    scanC_kernel<<<SCAN_BLOCKS, 1024, 0, s_csr>>>();
    scatter_kernel<<<(TOT_E + 1023) / 1024, 1024, 0, s_csr>>>(ei);
    cudaEventRecord(e_join, s_csr);

    // main chain (legacy stream): proj + conv1 transform/attention
    proj_kernel<<<(N_NODES + 127) / 128, 256>>>(x, projW, projB, bn1g, bn1b, bn1m, bn1v);
    xw64_kernel<<<(N_NODES + 63) / 64, 256>>>(0, W1);
    att_kernel<8><<<(N_NODES * 8 + 255) / 256, 256>>>(as1, ad1);

    // join: gathers need the CSR
    cudaStreamWaitEvent(0, e_join, 0);

    gather_kernel<8><<<(N_NODES * 32 + 255) / 256, 256>>>(b1);
    post_kernel<<<(N_NODES * 16 + 255) / 256, 256>>>(0, bn2g, bn2b, bn2m, bn2v);

    // GAT conv 2 (H=1)
    xw64_kernel<<<(N_NODES + 63) / 64, 256>>>(1, W2);
    att_kernel<1><<<(N_NODES + 255) / 256, 256>>>(as2, ad2);
    gather_kernel<1><<<(N_NODES * 32 + 255) / 256, 256>>>(b2);
    post_kernel<<<(N_NODES * 16 + 255) / 256, 256>>>(1, bn3g, bn3b, bn3m, bn3v);

    // classifier
    cls_kernel<<<(N_NODES + 31) / 32, 256>>>(clsW, clsB, out);

    cudaEventDestroy(e_fork);
    cudaEventDestroy(e_join);
    cudaStreamDestroy(s_csr);
}